// round 11
// baseline (speedup 1.0000x reference)
#include <cuda_runtime.h>
#include <cuda_bf16.h>
#include <cstdint>
#include <cstddef>

// Problem constants
#define S_LEN   2048
#define HID     4096
#define NH      32
#define NKV     8
#define HD      128
#define NQD     (NH*HD)    // 4096
#define NKD     (NKV*HD)   // 1024
#define INIT_W  128
#define RECENT_W 512
#define HEAVY_W 512
#define SCALE_F 0.08838834764831845f   // 1/sqrt(128)

// ---------------- device scratch (static, no allocation) ----------------
__device__ float    g_q [(size_t)S_LEN * NQD];          // 32 MB
__device__ float    g_k [(size_t)S_LEN * NKD];          // 8 MB
__device__ float    g_v [(size_t)S_LEN * NKD];          // 8 MB
__device__ float    g_o [(size_t)S_LEN * NQD];          // 32 MB
__device__ float    g_sc[(size_t)NH * S_LEN * S_LEN];   // 512 MB score scratch
__device__ unsigned g_thr[(size_t)NH * S_LEN];          // per-row top-k threshold (uint key)

// ---------------- generic fp32 SGEMM: C[M,N] = A[M,K] @ B[K,N], row-major, all dims multiples of tile ----------------
#define GBM 128
#define GBN 128
#define GBK 16
__global__ __launch_bounds__(256)
void sgemm_kernel(const float* __restrict__ A, const float* __restrict__ B,
                  float* __restrict__ C, int M, int N, int K)
{
    __shared__ float As[GBK][GBM + 4];   // transposed A tile, padded
    __shared__ float Bs[GBK][GBN];

    const int tid = threadIdx.x;
    const int bm = blockIdx.y * GBM;
    const int bn = blockIdx.x * GBN;

    const int arow = tid >> 2;          // 0..63
    const int acol = (tid & 3) << 2;    // 0,4,8,12
    const int brow = tid >> 5;          // 0..7
    const int bcol = (tid & 31) << 2;   // 0..124

    const int ty = tid >> 4;            // 0..15
    const int tx = tid & 15;            // 0..15

    float acc[8][8];
#pragma unroll
    for (int i = 0; i < 8; i++)
#pragma unroll
        for (int j = 0; j < 8; j++) acc[i][j] = 0.f;

    for (int k0 = 0; k0 < K; k0 += GBK) {
#pragma unroll
        for (int h = 0; h < 2; h++) {
            int r = arow + h * 64;
            float4 av = *(const float4*)(A + (size_t)(bm + r) * K + k0 + acol);
            As[acol + 0][r] = av.x;
            As[acol + 1][r] = av.y;
            As[acol + 2][r] = av.z;
            As[acol + 3][r] = av.w;
        }
#pragma unroll
        for (int h = 0; h < 2; h++) {
            int r = brow + h * 8;
            *(float4*)(&Bs[r][bcol]) = *(const float4*)(B + (size_t)(k0 + r) * N + bn + bcol);
        }
        __syncthreads();

#pragma unroll
        for (int kk = 0; kk < GBK; kk++) {
            float a[8], b[8];
            *(float4*)(a)     = *(const float4*)(&As[kk][ty * 8]);
            *(float4*)(a + 4) = *(const float4*)(&As[kk][ty * 8 + 4]);
            *(float4*)(b)     = *(const float4*)(&Bs[kk][tx * 8]);
            *(float4*)(b + 4) = *(const float4*)(&Bs[kk][tx * 8 + 4]);
#pragma unroll
            for (int i = 0; i < 8; i++)
#pragma unroll
                for (int j = 0; j < 8; j++)
                    acc[i][j] += a[i] * b[j];
        }
        __syncthreads();
    }

#pragma unroll
    for (int i = 0; i < 8; i++) {
        float* crow = C + (size_t)(bm + ty * 8 + i) * N + bn + tx * 8;
        *(float4*)(crow)     = make_float4(acc[i][0], acc[i][1], acc[i][2], acc[i][3]);
        *(float4*)(crow + 4) = make_float4(acc[i][4], acc[i][5], acc[i][6], acc[i][7]);
    }
}

// ---------------- RoPE: in-place on Q rows [S, 4096] and K rows [S, 1024] ----------------
__global__ void rope_kernel(float* __restrict__ Q, float* __restrict__ Kb)
{
    int s = blockIdx.x;           // 0..2047
    int h = blockIdx.y;           // 0..NH+NKV-1
    int j = threadIdx.x;          // 0..63

    float inv = powf(10000.0f, -(float)j / 64.0f);
    float ang = (float)s * inv;
    float c = cosf(ang);
    float sn = sinf(ang);

    float* base;
    if (h < NH) base = Q + (size_t)s * NQD + h * HD;
    else        base = Kb + (size_t)s * NKD + (h - NH) * HD;

    float x1 = base[j];
    float x2 = base[j + 64];
    base[j]      = x1 * c - x2 * sn;
    base[j + 64] = x2 * c + x1 * sn;
}

// ---------------- scores: Sc[h][i][j] = sum_d Q[i,h*128+d] * K[j,(h/4)*128+d]  (64x64 tiles, causal tile skip) ----------------
__global__ __launch_bounds__(256)
void scores_kernel(const float* __restrict__ Q, const float* __restrict__ Kb,
                   float* __restrict__ Sc)
{
    int jt = blockIdx.x, it = blockIdx.y, h = blockIdx.z;
    if (jt > it) return;

    __shared__ float Qs[32][68];
    __shared__ float Ks[32][68];

    const int tid = threadIdx.x;
    const int lr  = tid >> 3;            // 0..31
    const int ld4 = (tid & 7) << 2;      // 0..28
    const int ty  = tid >> 4;            // 0..15
    const int tx  = tid & 15;            // 0..15

    const float* qbase = Q + (size_t)(it * 64) * NQD + h * HD;
    const float* kbase = Kb + (size_t)(jt * 64) * NKD + (h >> 2) * HD;

    float acc[4][4];
#pragma unroll
    for (int i = 0; i < 4; i++)
#pragma unroll
        for (int j = 0; j < 4; j++) acc[i][j] = 0.f;

    for (int d0 = 0; d0 < HD; d0 += 32) {
#pragma unroll
        for (int hh = 0; hh < 2; hh++) {
            int r = lr + hh * 32;
            float4 v = *(const float4*)(qbase + (size_t)r * NQD + d0 + ld4);
            Qs[ld4 + 0][r] = v.x; Qs[ld4 + 1][r] = v.y;
            Qs[ld4 + 2][r] = v.z; Qs[ld4 + 3][r] = v.w;
            float4 w = *(const float4*)(kbase + (size_t)r * NKD + d0 + ld4);
            Ks[ld4 + 0][r] = w.x; Ks[ld4 + 1][r] = w.y;
            Ks[ld4 + 2][r] = w.z; Ks[ld4 + 3][r] = w.w;
        }
        __syncthreads();
#pragma unroll
        for (int kk = 0; kk < 32; kk++) {
            float a[4], b[4];
            *(float4*)a = *(const float4*)(&Qs[kk][ty * 4]);
            *(float4*)b = *(const float4*)(&Ks[kk][tx * 4]);
#pragma unroll
            for (int i = 0; i < 4; i++)
#pragma unroll
                for (int j = 0; j < 4; j++)
                    acc[i][j] += a[i] * b[j];
        }
        __syncthreads();
    }

    float* out = Sc + ((size_t)h * S_LEN + it * 64 + ty * 4) * S_LEN + jt * 64 + tx * 4;
#pragma unroll
    for (int i = 0; i < 4; i++)
        *(float4*)(out + (size_t)i * S_LEN) =
            make_float4(acc[i][0], acc[i][1], acc[i][2], acc[i][3]);
}

// ---------------- top-k threshold: warp radix-select 512th largest over middle band [128, i-512] ----------------
__device__ __forceinline__ unsigned f2key(float f)
{
    unsigned b = __float_as_uint(f);
    return (b & 0x80000000u) ? ~b : (b ^ 0x80000000u);
}

__global__ __launch_bounds__(256)
void topk_kernel(const float* __restrict__ Sc, unsigned* __restrict__ Thr)
{
    __shared__ unsigned hist[8][256];

    const int h    = blockIdx.x;
    const int warp = threadIdx.x >> 5;
    const int lane = threadIdx.x & 31;
    const int i    = 1152 + blockIdx.y * 8 + warp;   // only rows where selection matters

    const float* row = Sc + ((size_t)h * S_LEN + i) * S_LEN + INIT_W;
    const int w = i - 639;                           // middle width, 513..1408

    unsigned prefix = 0;
    int k = HEAVY_W;                                 // rank from top (1-based)

    for (int shift = 24; shift >= 0; shift -= 8) {
        for (int b = lane; b < 256; b += 32) hist[warp][b] = 0;
        __syncwarp();

        unsigned mask_hi = (shift == 24) ? 0u : (0xFFFFFFFFu << (shift + 8));
        for (int idx = lane; idx < w; idx += 32) {
            unsigned u = f2key(row[idx]);
            if ((u & mask_hi) == prefix)
                atomicAdd(&hist[warp][(u >> shift) & 0xFFu], 1u);
        }
        __syncwarp();

        if (lane == 0) {
            int cum = 0;
            int sel = 0;
            for (int b = 255; b >= 0; b--) {
                int c = (int)hist[warp][b];
                if (cum + c >= k) { sel = b; break; }
                cum += c;
            }
            k -= cum;
            prefix |= ((unsigned)sel) << shift;
            hist[warp][0] = prefix;
            hist[warp][1] = (unsigned)k;
        }
        __syncwarp();
        prefix = hist[warp][0];
        k = (int)hist[warp][1];
        __syncwarp();
    }

    if (lane == 0) Thr[h * S_LEN + i] = prefix;
}

// ---------------- masked softmax (in-place on score rows) + P@V ----------------
__device__ __forceinline__ float warpMax(float v)
{
#pragma unroll
    for (int o = 16; o; o >>= 1) v = fmaxf(v, __shfl_xor_sync(0xffffffffu, v, o));
    return v;
}
__device__ __forceinline__ float warpSum(float v)
{
#pragma unroll
    for (int o = 16; o; o >>= 1) v += __shfl_xor_sync(0xffffffffu, v, o);
    return v;
}

__global__ __launch_bounds__(256)
void attn_kernel(float* __restrict__ Sc, const unsigned* __restrict__ Thr,
                 const float* __restrict__ Vb, float* __restrict__ O)
{
    __shared__ float Vs[32][128];
    __shared__ float rsum[32];

    const int h   = blockIdx.x;
    const int q0  = blockIdx.y * 32;
    const int kvh = h >> 2;
    const int tid = threadIdx.x;
    const int lane = tid & 31;
    const int warp = tid >> 5;

    // ---- phase A: per-row masked softmax (unnormalized), warp handles 4 rows ----
    for (int t = 0; t < 4; t++) {
        int r = (warp << 2) + t;
        int i = q0 + r;
        float* row = Sc + ((size_t)h * S_LEN + i) * S_LEN;
        unsigned T = (i >= 1152) ? Thr[h * S_LEN + i] : 0u;
        int mid_hi = i - RECENT_W;

        float m = -3.4e38f;
        for (int j = lane; j <= i; j += 32) {
            float s = row[j];
            bool sel = true;
            if (j >= INIT_W && j <= mid_hi) sel = (f2key(s) >= T);
            if (sel) m = fmaxf(m, s);
        }
        m = warpMax(m);

        float sum = 0.f;
        for (int j = lane; j <= i; j += 32) {
            float s = row[j];
            bool sel = true;
            if (j >= INIT_W && j <= mid_hi) sel = (f2key(s) >= T);
            float e = sel ? expf((s - m) * SCALE_F) : 0.f;
            row[j] = e;
            sum += e;
        }
        sum = warpSum(sum);

        for (int j = i + 1 + lane; j <= q0 + 31; j += 32) row[j] = 0.f;
        if (lane == 0) rsum[r] = sum;
    }
    __syncthreads();

    // ---- phase B: O[rows q0..q0+31, h*128..+127] = P @ V ----
    const int tr = tid >> 4;              // 0..15 -> rows 2tr, 2tr+1
    const int c0 = (tid & 15) << 3;       // output column base (8 cols)

    float acc0[8], acc1[8];
#pragma unroll
    for (int c = 0; c < 8; c++) { acc0[c] = 0.f; acc1[c] = 0.f; }

    const float* row0 = Sc + ((size_t)h * S_LEN + q0 + 2 * tr) * S_LEN;
    const float* row1 = row0 + S_LEN;

    for (int jc = 0; jc <= q0 + 31; jc += 32) {
#pragma unroll
        for (int p = 0; p < 4; p++) {
            int f4 = tid + p * 256;
            int vr = f4 >> 5;
            int vc = (f4 & 31) << 2;
            *(float4*)(&Vs[vr][vc]) =
                *(const float4*)(Vb + (size_t)(jc + vr) * NKD + kvh * HD + vc);
        }
        __syncthreads();

#pragma unroll 8
        for (int jj = 0; jj < 32; jj++) {
            float p0 = row0[jc + jj];
            float p1 = row1[jc + jj];
            float4 va = *(const float4*)(&Vs[jj][c0]);
            float4 vb = *(const float4*)(&Vs[jj][c0 + 4]);
            acc0[0] += p0 * va.x; acc0[1] += p0 * va.y;
            acc0[2] += p0 * va.z; acc0[3] += p0 * va.w;
            acc0[4] += p0 * vb.x; acc0[5] += p0 * vb.y;
            acc0[6] += p0 * vb.z; acc0[7] += p0 * vb.w;
            acc1[0] += p1 * va.x; acc1[1] += p1 * va.y;
            acc1[2] += p1 * va.z; acc1[3] += p1 * va.w;
            acc1[4] += p1 * vb.x; acc1[5] += p1 * vb.y;
            acc1[6] += p1 * vb.z; acc1[7] += p1 * vb.w;
        }
        __syncthreads();
    }

    float inv0 = 1.f / rsum[2 * tr];
    float inv1 = 1.f / rsum[2 * tr + 1];
    float* o0 = O + (size_t)(q0 + 2 * tr) * NQD + h * HD + c0;
    float* o1 = o0 + NQD;
    *(float4*)(o0)     = make_float4(acc0[0] * inv0, acc0[1] * inv0, acc0[2] * inv0, acc0[3] * inv0);
    *(float4*)(o0 + 4) = make_float4(acc0[4] * inv0, acc0[5] * inv0, acc0[6] * inv0, acc0[7] * inv0);
    *(float4*)(o1)     = make_float4(acc1[0] * inv1, acc1[1] * inv1, acc1[2] * inv1, acc1[3] * inv1);
    *(float4*)(o1 + 4) = make_float4(acc1[4] * inv1, acc1[5] * inv1, acc1[6] * inv1, acc1[7] * inv1);
}

// ---------------- launch ----------------
extern "C" void kernel_launch(void* const* d_in, const int* in_sizes, int n_in,
                              void* d_out, int out_size)
{
    (void)in_sizes; (void)n_in; (void)out_size;

    const float* H  = (const float*)d_in[0];
    const float* wq = (const float*)d_in[1];
    const float* wk = (const float*)d_in[2];
    const float* wv = (const float*)d_in[3];
    const float* wo = (const float*)d_in[4];
    float* out = (float*)d_out;

    float *Q, *K, *V, *O, *Sc;
    unsigned* Thr;
    cudaGetSymbolAddress((void**)&Q,   g_q);
    cudaGetSymbolAddress((void**)&K,   g_k);
    cudaGetSymbolAddress((void**)&V,   g_v);
    cudaGetSymbolAddress((void**)&O,   g_o);
    cudaGetSymbolAddress((void**)&Sc,  g_sc);
    cudaGetSymbolAddress((void**)&Thr, g_thr);

    // QKV projections
    sgemm_kernel<<<dim3(NQD / GBN, S_LEN / GBM), 256>>>(H, wq, Q, S_LEN, NQD, HID);
    sgemm_kernel<<<dim3(NKD / GBN, S_LEN / GBM), 256>>>(H, wk, K, S_LEN, NKD, HID);
    sgemm_kernel<<<dim3(NKD / GBN, S_LEN / GBM), 256>>>(H, wv, V, S_LEN, NKD, HID);

    // RoPE on Q and K
    rope_kernel<<<dim3(S_LEN, NH + NKV), 64>>>(Q, K);

    // raw attention scores (causal tiles only)
    scores_kernel<<<dim3(S_LEN / 64, S_LEN / 64, NH), 256>>>(Q, K, Sc);

    // heavy-hitter thresholds (rows 1152..2047)
    topk_kernel<<<dim3(NH, (S_LEN - 1152) / 8), 256>>>(Sc, Thr);

    // masked softmax + P@V
    attn_kernel<<<dim3(NH, S_LEN / 32), 256>>>(Sc, Thr, V, O);

    // output projection
    sgemm_kernel<<<dim3(HID / GBN, S_LEN / GBM), 256>>>(O, wo, out, S_LEN, HID, NQD);
}

// round 12
// speedup vs baseline: 1.0010x; 1.0010x over previous
#include <cuda_runtime.h>
#include <cuda_bf16.h>
#include <cstdint>
#include <cstddef>

// Problem constants
#define S_LEN   2048
#define HID     4096
#define NH      32
#define NKV     8
#define HD      128
#define NQD     (NH*HD)    // 4096
#define NKD     (NKV*HD)   // 1024
#define INIT_W  128
#define RECENT_W 512
#define HEAVY_W 512
#define SCALE_F 0.08838834764831845f   // 1/sqrt(128)

// ---------------- device scratch (static, no allocation) ----------------
__device__ float    g_q [(size_t)S_LEN * NQD];          // 32 MB
__device__ float    g_k [(size_t)S_LEN * NKD];          // 8 MB
__device__ float    g_v [(size_t)S_LEN * NKD];          // 8 MB
__device__ float    g_o [(size_t)S_LEN * NQD];          // 32 MB
__device__ float    g_sc[(size_t)NH * S_LEN * S_LEN];   // 512 MB score scratch
__device__ unsigned g_thr[(size_t)NH * S_LEN];          // per-row top-k threshold (uint key)

// ---------------- generic fp32 SGEMM: C[M,N] = A[M,K] @ B[K,N], row-major, all dims multiples of tile ----------------
#define GBM 128
#define GBN 128
#define GBK 16
__global__ __launch_bounds__(256)
void sgemm_kernel(const float* __restrict__ A, const float* __restrict__ B,
                  float* __restrict__ C, int M, int N, int K)
{
    __shared__ float As[GBK][GBM + 4];   // transposed A tile, padded
    __shared__ float Bs[GBK][GBN];

    const int tid = threadIdx.x;
    const int bm = blockIdx.y * GBM;
    const int bn = blockIdx.x * GBN;

    const int arow = tid >> 2;          // 0..63
    const int acol = (tid & 3) << 2;    // 0,4,8,12
    const int brow = tid >> 5;          // 0..7
    const int bcol = (tid & 31) << 2;   // 0..124

    const int ty = tid >> 4;            // 0..15
    const int tx = tid & 15;            // 0..15

    float acc[8][8];
#pragma unroll
    for (int i = 0; i < 8; i++)
#pragma unroll
        for (int j = 0; j < 8; j++) acc[i][j] = 0.f;

    for (int k0 = 0; k0 < K; k0 += GBK) {
#pragma unroll
        for (int h = 0; h < 2; h++) {
            int r = arow + h * 64;
            float4 av = *(const float4*)(A + (size_t)(bm + r) * K + k0 + acol);
            As[acol + 0][r] = av.x;
            As[acol + 1][r] = av.y;
            As[acol + 2][r] = av.z;
            As[acol + 3][r] = av.w;
        }
#pragma unroll
        for (int h = 0; h < 2; h++) {
            int r = brow + h * 8;
            *(float4*)(&Bs[r][bcol]) = *(const float4*)(B + (size_t)(k0 + r) * N + bn + bcol);
        }
        __syncthreads();

#pragma unroll
        for (int kk = 0; kk < GBK; kk++) {
            float a[8], b[8];
            *(float4*)(a)     = *(const float4*)(&As[kk][ty * 8]);
            *(float4*)(a + 4) = *(const float4*)(&As[kk][ty * 8 + 4]);
            *(float4*)(b)     = *(const float4*)(&Bs[kk][tx * 8]);
            *(float4*)(b + 4) = *(const float4*)(&Bs[kk][tx * 8 + 4]);
#pragma unroll
            for (int i = 0; i < 8; i++)
#pragma unroll
                for (int j = 0; j < 8; j++)
                    acc[i][j] += a[i] * b[j];
        }
        __syncthreads();
    }

#pragma unroll
    for (int i = 0; i < 8; i++) {
        float* crow = C + (size_t)(bm + ty * 8 + i) * N + bn + tx * 8;
        *(float4*)(crow)     = make_float4(acc[i][0], acc[i][1], acc[i][2], acc[i][3]);
        *(float4*)(crow + 4) = make_float4(acc[i][4], acc[i][5], acc[i][6], acc[i][7]);
    }
}

// ---------------- RoPE: in-place on Q rows [S, 4096] and K rows [S, 1024] ----------------
__global__ void rope_kernel(float* __restrict__ Q, float* __restrict__ Kb)
{
    int s = blockIdx.x;           // 0..2047
    int h = blockIdx.y;           // 0..NH+NKV-1
    int j = threadIdx.x;          // 0..63

    float inv = powf(10000.0f, -(float)j / 64.0f);
    float ang = (float)s * inv;
    float c = cosf(ang);
    float sn = sinf(ang);

    float* base;
    if (h < NH) base = Q + (size_t)s * NQD + h * HD;
    else        base = Kb + (size_t)s * NKD + (h - NH) * HD;

    float x1 = base[j];
    float x2 = base[j + 64];
    base[j]      = x1 * c - x2 * sn;
    base[j + 64] = x2 * c + x1 * sn;
}

// ---------------- scores: Sc[h][i][j] = sum_d Q[i,h*128+d] * K[j,(h/4)*128+d]  (64x64 tiles, causal tile skip) ----------------
__global__ __launch_bounds__(256)
void scores_kernel(const float* __restrict__ Q, const float* __restrict__ Kb,
                   float* __restrict__ Sc)
{
    int jt = blockIdx.x, it = blockIdx.y, h = blockIdx.z;
    if (jt > it) return;

    __shared__ float Qs[32][68];
    __shared__ float Ks[32][68];

    const int tid = threadIdx.x;
    const int lr  = tid >> 3;            // 0..31
    const int ld4 = (tid & 7) << 2;      // 0..28
    const int ty  = tid >> 4;            // 0..15
    const int tx  = tid & 15;            // 0..15

    const float* qbase = Q + (size_t)(it * 64) * NQD + h * HD;
    const float* kbase = Kb + (size_t)(jt * 64) * NKD + (h >> 2) * HD;

    float acc[4][4];
#pragma unroll
    for (int i = 0; i < 4; i++)
#pragma unroll
        for (int j = 0; j < 4; j++) acc[i][j] = 0.f;

    for (int d0 = 0; d0 < HD; d0 += 32) {
#pragma unroll
        for (int hh = 0; hh < 2; hh++) {
            int r = lr + hh * 32;
            float4 v = *(const float4*)(qbase + (size_t)r * NQD + d0 + ld4);
            Qs[ld4 + 0][r] = v.x; Qs[ld4 + 1][r] = v.y;
            Qs[ld4 + 2][r] = v.z; Qs[ld4 + 3][r] = v.w;
            float4 w = *(const float4*)(kbase + (size_t)r * NKD + d0 + ld4);
            Ks[ld4 + 0][r] = w.x; Ks[ld4 + 1][r] = w.y;
            Ks[ld4 + 2][r] = w.z; Ks[ld4 + 3][r] = w.w;
        }
        __syncthreads();
#pragma unroll
        for (int kk = 0; kk < 32; kk++) {
            float a[4], b[4];
            *(float4*)a = *(const float4*)(&Qs[kk][ty * 4]);
            *(float4*)b = *(const float4*)(&Ks[kk][tx * 4]);
#pragma unroll
            for (int i = 0; i < 4; i++)
#pragma unroll
                for (int j = 0; j < 4; j++)
                    acc[i][j] += a[i] * b[j];
        }
        __syncthreads();
    }

    float* out = Sc + ((size_t)h * S_LEN + it * 64 + ty * 4) * S_LEN + jt * 64 + tx * 4;
#pragma unroll
    for (int i = 0; i < 4; i++)
        *(float4*)(out + (size_t)i * S_LEN) =
            make_float4(acc[i][0], acc[i][1], acc[i][2], acc[i][3]);
}

// ---------------- top-k threshold: warp radix-select 512th largest over middle band [128, i-512] ----------------
__device__ __forceinline__ unsigned f2key(float f)
{
    unsigned b = __float_as_uint(f);
    return (b & 0x80000000u) ? ~b : (b ^ 0x80000000u);
}

__global__ __launch_bounds__(256)
void topk_kernel(const float* __restrict__ Sc, unsigned* __restrict__ Thr)
{
    __shared__ unsigned hist[8][256];

    const int h    = blockIdx.x;
    const int warp = threadIdx.x >> 5;
    const int lane = threadIdx.x & 31;
    const int i    = 1152 + blockIdx.y * 8 + warp;   // only rows where selection matters

    const float* row = Sc + ((size_t)h * S_LEN + i) * S_LEN + INIT_W;
    const int w = i - 639;                           // middle width, 513..1408

    unsigned prefix = 0;
    int k = HEAVY_W;                                 // rank from top (1-based)

    for (int shift = 24; shift >= 0; shift -= 8) {
        for (int b = lane; b < 256; b += 32) hist[warp][b] = 0;
        __syncwarp();

        unsigned mask_hi = (shift == 24) ? 0u : (0xFFFFFFFFu << (shift + 8));
        for (int idx = lane; idx < w; idx += 32) {
            unsigned u = f2key(row[idx]);
            if ((u & mask_hi) == prefix)
                atomicAdd(&hist[warp][(u >> shift) & 0xFFu], 1u);
        }
        __syncwarp();

        if (lane == 0) {
            int cum = 0;
            int sel = 0;
            for (int b = 255; b >= 0; b--) {
                int c = (int)hist[warp][b];
                if (cum + c >= k) { sel = b; break; }
                cum += c;
            }
            k -= cum;
            prefix |= ((unsigned)sel) << shift;
            hist[warp][0] = prefix;
            hist[warp][1] = (unsigned)k;
        }
        __syncwarp();
        prefix = hist[warp][0];
        k = (int)hist[warp][1];
        __syncwarp();
    }

    if (lane == 0) Thr[h * S_LEN + i] = prefix;
}

// ---------------- masked softmax (in-place on score rows) + P@V ----------------
__device__ __forceinline__ float warpMax(float v)
{
#pragma unroll
    for (int o = 16; o; o >>= 1) v = fmaxf(v, __shfl_xor_sync(0xffffffffu, v, o));
    return v;
}
__device__ __forceinline__ float warpSum(float v)
{
#pragma unroll
    for (int o = 16; o; o >>= 1) v += __shfl_xor_sync(0xffffffffu, v, o);
    return v;
}

__global__ __launch_bounds__(256)
void attn_kernel(float* __restrict__ Sc, const unsigned* __restrict__ Thr,
                 const float* __restrict__ Vb, float* __restrict__ O)
{
    __shared__ float Vs[32][128];
    __shared__ float rsum[32];

    const int h   = blockIdx.x;
    const int q0  = blockIdx.y * 32;
    const int kvh = h >> 2;
    const int tid = threadIdx.x;
    const int lane = tid & 31;
    const int warp = tid >> 5;

    // ---- phase A: per-row masked softmax (unnormalized), warp handles 4 rows ----
    for (int t = 0; t < 4; t++) {
        int r = (warp << 2) + t;
        int i = q0 + r;
        float* row = Sc + ((size_t)h * S_LEN + i) * S_LEN;
        unsigned T = (i >= 1152) ? Thr[h * S_LEN + i] : 0u;
        int mid_hi = i - RECENT_W;

        float m = -3.4e38f;
        for (int j = lane; j <= i; j += 32) {
            float s = row[j];
            bool sel = true;
            if (j >= INIT_W && j <= mid_hi) sel = (f2key(s) >= T);
            if (sel) m = fmaxf(m, s);
        }
        m = warpMax(m);

        float sum = 0.f;
        for (int j = lane; j <= i; j += 32) {
            float s = row[j];
            bool sel = true;
            if (j >= INIT_W && j <= mid_hi) sel = (f2key(s) >= T);
            float e = sel ? expf((s - m) * SCALE_F) : 0.f;
            row[j] = e;
            sum += e;
        }
        sum = warpSum(sum);

        for (int j = i + 1 + lane; j <= q0 + 31; j += 32) row[j] = 0.f;
        if (lane == 0) rsum[r] = sum;
    }
    __syncthreads();

    // ---- phase B: O[rows q0..q0+31, h*128..+127] = P @ V ----
    const int tr = tid >> 4;              // 0..15 -> rows 2tr, 2tr+1
    const int c0 = (tid & 15) << 3;       // output column base (8 cols)

    float acc0[8], acc1[8];
#pragma unroll
    for (int c = 0; c < 8; c++) { acc0[c] = 0.f; acc1[c] = 0.f; }

    const float* row0 = Sc + ((size_t)h * S_LEN + q0 + 2 * tr) * S_LEN;
    const float* row1 = row0 + S_LEN;

    for (int jc = 0; jc <= q0 + 31; jc += 32) {
#pragma unroll
        for (int p = 0; p < 4; p++) {
            int f4 = tid + p * 256;
            int vr = f4 >> 5;
            int vc = (f4 & 31) << 2;
            *(float4*)(&Vs[vr][vc]) =
                *(const float4*)(Vb + (size_t)(jc + vr) * NKD + kvh * HD + vc);
        }
        __syncthreads();

#pragma unroll 8
        for (int jj = 0; jj < 32; jj++) {
            float p0 = row0[jc + jj];
            float p1 = row1[jc + jj];
            float4 va = *(const float4*)(&Vs[jj][c0]);
            float4 vb = *(const float4*)(&Vs[jj][c0 + 4]);
            acc0[0] += p0 * va.x; acc0[1] += p0 * va.y;
            acc0[2] += p0 * va.z; acc0[3] += p0 * va.w;
            acc0[4] += p0 * vb.x; acc0[5] += p0 * vb.y;
            acc0[6] += p0 * vb.z; acc0[7] += p0 * vb.w;
            acc1[0] += p1 * va.x; acc1[1] += p1 * va.y;
            acc1[2] += p1 * va.z; acc1[3] += p1 * va.w;
            acc1[4] += p1 * vb.x; acc1[5] += p1 * vb.y;
            acc1[6] += p1 * vb.z; acc1[7] += p1 * vb.w;
        }
        __syncthreads();
    }

    float inv0 = 1.f / rsum[2 * tr];
    float inv1 = 1.f / rsum[2 * tr + 1];
    float* o0 = O + (size_t)(q0 + 2 * tr) * NQD + h * HD + c0;
    float* o1 = o0 + NQD;
    *(float4*)(o0)     = make_float4(acc0[0] * inv0, acc0[1] * inv0, acc0[2] * inv0, acc0[3] * inv0);
    *(float4*)(o0 + 4) = make_float4(acc0[4] * inv0, acc0[5] * inv0, acc0[6] * inv0, acc0[7] * inv0);
    *(float4*)(o1)     = make_float4(acc1[0] * inv1, acc1[1] * inv1, acc1[2] * inv1, acc1[3] * inv1);
    *(float4*)(o1 + 4) = make_float4(acc1[4] * inv1, acc1[5] * inv1, acc1[6] * inv1, acc1[7] * inv1);
}

// ---------------- launch ----------------
extern "C" void kernel_launch(void* const* d_in, const int* in_sizes, int n_in,
                              void* d_out, int out_size)
{
    (void)in_sizes; (void)n_in; (void)out_size;

    const float* H  = (const float*)d_in[0];
    const float* wq = (const float*)d_in[1];
    const float* wk = (const float*)d_in[2];
    const float* wv = (const float*)d_in[3];
    const float* wo = (const float*)d_in[4];
    float* out = (float*)d_out;

    float *Q, *K, *V, *O, *Sc;
    unsigned* Thr;
    cudaGetSymbolAddress((void**)&Q,   g_q);
    cudaGetSymbolAddress((void**)&K,   g_k);
    cudaGetSymbolAddress((void**)&V,   g_v);
    cudaGetSymbolAddress((void**)&O,   g_o);
    cudaGetSymbolAddress((void**)&Sc,  g_sc);
    cudaGetSymbolAddress((void**)&Thr, g_thr);

    // QKV projections
    sgemm_kernel<<<dim3(NQD / GBN, S_LEN / GBM), 256>>>(H, wq, Q, S_LEN, NQD, HID);
    sgemm_kernel<<<dim3(NKD / GBN, S_LEN / GBM), 256>>>(H, wk, K, S_LEN, NKD, HID);
    sgemm_kernel<<<dim3(NKD / GBN, S_LEN / GBM), 256>>>(H, wv, V, S_LEN, NKD, HID);

    // RoPE on Q and K
    rope_kernel<<<dim3(S_LEN, NH + NKV), 64>>>(Q, K);

    // raw attention scores (causal tiles only)
    scores_kernel<<<dim3(S_LEN / 64, S_LEN / 64, NH), 256>>>(Q, K, Sc);

    // heavy-hitter thresholds (rows 1152..2047)
    topk_kernel<<<dim3(NH, (S_LEN - 1152) / 8), 256>>>(Sc, Thr);

    // masked softmax + P@V
    attn_kernel<<<dim3(NH, S_LEN / 32), 256>>>(Sc, Thr, V, O);

    // output projection
    sgemm_kernel<<<dim3(HID / GBN, S_LEN / GBM), 256>>>(O, wo, out, S_LEN, HID, NQD);
}

// round 13
// speedup vs baseline: 1.0011x; 1.0001x over previous
#include <cuda_runtime.h>
#include <cuda_bf16.h>
#include <cstdint>
#include <cstddef>

// Problem constants
#define S_LEN   2048
#define HID     4096
#define NH      32
#define NKV     8
#define HD      128
#define NQD     (NH*HD)    // 4096
#define NKD     (NKV*HD)   // 1024
#define INIT_W  128
#define RECENT_W 512
#define HEAVY_W 512
#define SCALE_F 0.08838834764831845f   // 1/sqrt(128)

// ---------------- device scratch (static, no allocation) ----------------
__device__ float    g_q [(size_t)S_LEN * NQD];          // 32 MB
__device__ float    g_k [(size_t)S_LEN * NKD];          // 8 MB
__device__ float    g_v [(size_t)S_LEN * NKD];          // 8 MB
__device__ float    g_o [(size_t)S_LEN * NQD];          // 32 MB
__device__ float    g_sc[(size_t)NH * S_LEN * S_LEN];   // 512 MB score scratch
__device__ unsigned g_thr[(size_t)NH * S_LEN];          // per-row top-k threshold (uint key)

// ---------------- generic fp32 SGEMM: C[M,N] = A[M,K] @ B[K,N], row-major, all dims multiples of tile ----------------
#define GBM 128
#define GBN 128
#define GBK 16
__global__ __launch_bounds__(256)
void sgemm_kernel(const float* __restrict__ A, const float* __restrict__ B,
                  float* __restrict__ C, int M, int N, int K)
{
    __shared__ float As[GBK][GBM + 4];   // transposed A tile, padded
    __shared__ float Bs[GBK][GBN];

    const int tid = threadIdx.x;
    const int bm = blockIdx.y * GBM;
    const int bn = blockIdx.x * GBN;

    const int arow = tid >> 2;          // 0..63
    const int acol = (tid & 3) << 2;    // 0,4,8,12
    const int brow = tid >> 5;          // 0..7
    const int bcol = (tid & 31) << 2;   // 0..124

    const int ty = tid >> 4;            // 0..15
    const int tx = tid & 15;            // 0..15

    float acc[8][8];
#pragma unroll
    for (int i = 0; i < 8; i++)
#pragma unroll
        for (int j = 0; j < 8; j++) acc[i][j] = 0.f;

    for (int k0 = 0; k0 < K; k0 += GBK) {
#pragma unroll
        for (int h = 0; h < 2; h++) {
            int r = arow + h * 64;
            float4 av = *(const float4*)(A + (size_t)(bm + r) * K + k0 + acol);
            As[acol + 0][r] = av.x;
            As[acol + 1][r] = av.y;
            As[acol + 2][r] = av.z;
            As[acol + 3][r] = av.w;
        }
#pragma unroll
        for (int h = 0; h < 2; h++) {
            int r = brow + h * 8;
            *(float4*)(&Bs[r][bcol]) = *(const float4*)(B + (size_t)(k0 + r) * N + bn + bcol);
        }
        __syncthreads();

#pragma unroll
        for (int kk = 0; kk < GBK; kk++) {
            float a[8], b[8];
            *(float4*)(a)     = *(const float4*)(&As[kk][ty * 8]);
            *(float4*)(a + 4) = *(const float4*)(&As[kk][ty * 8 + 4]);
            *(float4*)(b)     = *(const float4*)(&Bs[kk][tx * 8]);
            *(float4*)(b + 4) = *(const float4*)(&Bs[kk][tx * 8 + 4]);
#pragma unroll
            for (int i = 0; i < 8; i++)
#pragma unroll
                for (int j = 0; j < 8; j++)
                    acc[i][j] += a[i] * b[j];
        }
        __syncthreads();
    }

#pragma unroll
    for (int i = 0; i < 8; i++) {
        float* crow = C + (size_t)(bm + ty * 8 + i) * N + bn + tx * 8;
        *(float4*)(crow)     = make_float4(acc[i][0], acc[i][1], acc[i][2], acc[i][3]);
        *(float4*)(crow + 4) = make_float4(acc[i][4], acc[i][5], acc[i][6], acc[i][7]);
    }
}

// ---------------- RoPE: in-place on Q rows [S, 4096] and K rows [S, 1024] ----------------
__global__ void rope_kernel(float* __restrict__ Q, float* __restrict__ Kb)
{
    int s = blockIdx.x;           // 0..2047
    int h = blockIdx.y;           // 0..NH+NKV-1
    int j = threadIdx.x;          // 0..63

    float inv = powf(10000.0f, -(float)j / 64.0f);
    float ang = (float)s * inv;
    float c = cosf(ang);
    float sn = sinf(ang);

    float* base;
    if (h < NH) base = Q + (size_t)s * NQD + h * HD;
    else        base = Kb + (size_t)s * NKD + (h - NH) * HD;

    float x1 = base[j];
    float x2 = base[j + 64];
    base[j]      = x1 * c - x2 * sn;
    base[j + 64] = x2 * c + x1 * sn;
}

// ---------------- scores: Sc[h][i][j] = sum_d Q[i,h*128+d] * K[j,(h/4)*128+d]  (64x64 tiles, causal tile skip) ----------------
__global__ __launch_bounds__(256)
void scores_kernel(const float* __restrict__ Q, const float* __restrict__ Kb,
                   float* __restrict__ Sc)
{
    int jt = blockIdx.x, it = blockIdx.y, h = blockIdx.z;
    if (jt > it) return;

    __shared__ float Qs[32][68];
    __shared__ float Ks[32][68];

    const int tid = threadIdx.x;
    const int lr  = tid >> 3;            // 0..31
    const int ld4 = (tid & 7) << 2;      // 0..28
    const int ty  = tid >> 4;            // 0..15
    const int tx  = tid & 15;            // 0..15

    const float* qbase = Q + (size_t)(it * 64) * NQD + h * HD;
    const float* kbase = Kb + (size_t)(jt * 64) * NKD + (h >> 2) * HD;

    float acc[4][4];
#pragma unroll
    for (int i = 0; i < 4; i++)
#pragma unroll
        for (int j = 0; j < 4; j++) acc[i][j] = 0.f;

    for (int d0 = 0; d0 < HD; d0 += 32) {
#pragma unroll
        for (int hh = 0; hh < 2; hh++) {
            int r = lr + hh * 32;
            float4 v = *(const float4*)(qbase + (size_t)r * NQD + d0 + ld4);
            Qs[ld4 + 0][r] = v.x; Qs[ld4 + 1][r] = v.y;
            Qs[ld4 + 2][r] = v.z; Qs[ld4 + 3][r] = v.w;
            float4 w = *(const float4*)(kbase + (size_t)r * NKD + d0 + ld4);
            Ks[ld4 + 0][r] = w.x; Ks[ld4 + 1][r] = w.y;
            Ks[ld4 + 2][r] = w.z; Ks[ld4 + 3][r] = w.w;
        }
        __syncthreads();
#pragma unroll
        for (int kk = 0; kk < 32; kk++) {
            float a[4], b[4];
            *(float4*)a = *(const float4*)(&Qs[kk][ty * 4]);
            *(float4*)b = *(const float4*)(&Ks[kk][tx * 4]);
#pragma unroll
            for (int i = 0; i < 4; i++)
#pragma unroll
                for (int j = 0; j < 4; j++)
                    acc[i][j] += a[i] * b[j];
        }
        __syncthreads();
    }

    float* out = Sc + ((size_t)h * S_LEN + it * 64 + ty * 4) * S_LEN + jt * 64 + tx * 4;
#pragma unroll
    for (int i = 0; i < 4; i++)
        *(float4*)(out + (size_t)i * S_LEN) =
            make_float4(acc[i][0], acc[i][1], acc[i][2], acc[i][3]);
}

// ---------------- top-k threshold: warp radix-select 512th largest over middle band [128, i-512] ----------------
__device__ __forceinline__ unsigned f2key(float f)
{
    unsigned b = __float_as_uint(f);
    return (b & 0x80000000u) ? ~b : (b ^ 0x80000000u);
}

__global__ __launch_bounds__(256)
void topk_kernel(const float* __restrict__ Sc, unsigned* __restrict__ Thr)
{
    __shared__ unsigned hist[8][256];

    const int h    = blockIdx.x;
    const int warp = threadIdx.x >> 5;
    const int lane = threadIdx.x & 31;
    const int i    = 1152 + blockIdx.y * 8 + warp;   // only rows where selection matters

    const float* row = Sc + ((size_t)h * S_LEN + i) * S_LEN + INIT_W;
    const int w = i - 639;                           // middle width, 513..1408

    unsigned prefix = 0;
    int k = HEAVY_W;                                 // rank from top (1-based)

    for (int shift = 24; shift >= 0; shift -= 8) {
        for (int b = lane; b < 256; b += 32) hist[warp][b] = 0;
        __syncwarp();

        unsigned mask_hi = (shift == 24) ? 0u : (0xFFFFFFFFu << (shift + 8));
        for (int idx = lane; idx < w; idx += 32) {
            unsigned u = f2key(row[idx]);
            if ((u & mask_hi) == prefix)
                atomicAdd(&hist[warp][(u >> shift) & 0xFFu], 1u);
        }
        __syncwarp();

        if (lane == 0) {
            int cum = 0;
            int sel = 0;
            for (int b = 255; b >= 0; b--) {
                int c = (int)hist[warp][b];
                if (cum + c >= k) { sel = b; break; }
                cum += c;
            }
            k -= cum;
            prefix |= ((unsigned)sel) << shift;
            hist[warp][0] = prefix;
            hist[warp][1] = (unsigned)k;
        }
        __syncwarp();
        prefix = hist[warp][0];
        k = (int)hist[warp][1];
        __syncwarp();
    }

    if (lane == 0) Thr[h * S_LEN + i] = prefix;
}

// ---------------- masked softmax (in-place on score rows) + P@V ----------------
__device__ __forceinline__ float warpMax(float v)
{
#pragma unroll
    for (int o = 16; o; o >>= 1) v = fmaxf(v, __shfl_xor_sync(0xffffffffu, v, o));
    return v;
}
__device__ __forceinline__ float warpSum(float v)
{
#pragma unroll
    for (int o = 16; o; o >>= 1) v += __shfl_xor_sync(0xffffffffu, v, o);
    return v;
}

__global__ __launch_bounds__(256)
void attn_kernel(float* __restrict__ Sc, const unsigned* __restrict__ Thr,
                 const float* __restrict__ Vb, float* __restrict__ O)
{
    __shared__ float Vs[32][128];
    __shared__ float rsum[32];

    const int h   = blockIdx.x;
    const int q0  = blockIdx.y * 32;
    const int kvh = h >> 2;
    const int tid = threadIdx.x;
    const int lane = tid & 31;
    const int warp = tid >> 5;

    // ---- phase A: per-row masked softmax (unnormalized), warp handles 4 rows ----
    for (int t = 0; t < 4; t++) {
        int r = (warp << 2) + t;
        int i = q0 + r;
        float* row = Sc + ((size_t)h * S_LEN + i) * S_LEN;
        unsigned T = (i >= 1152) ? Thr[h * S_LEN + i] : 0u;
        int mid_hi = i - RECENT_W;

        float m = -3.4e38f;
        for (int j = lane; j <= i; j += 32) {
            float s = row[j];
            bool sel = true;
            if (j >= INIT_W && j <= mid_hi) sel = (f2key(s) >= T);
            if (sel) m = fmaxf(m, s);
        }
        m = warpMax(m);

        float sum = 0.f;
        for (int j = lane; j <= i; j += 32) {
            float s = row[j];
            bool sel = true;
            if (j >= INIT_W && j <= mid_hi) sel = (f2key(s) >= T);
            float e = sel ? expf((s - m) * SCALE_F) : 0.f;
            row[j] = e;
            sum += e;
        }
        sum = warpSum(sum);

        for (int j = i + 1 + lane; j <= q0 + 31; j += 32) row[j] = 0.f;
        if (lane == 0) rsum[r] = sum;
    }
    __syncthreads();

    // ---- phase B: O[rows q0..q0+31, h*128..+127] = P @ V ----
    const int tr = tid >> 4;              // 0..15 -> rows 2tr, 2tr+1
    const int c0 = (tid & 15) << 3;       // output column base (8 cols)

    float acc0[8], acc1[8];
#pragma unroll
    for (int c = 0; c < 8; c++) { acc0[c] = 0.f; acc1[c] = 0.f; }

    const float* row0 = Sc + ((size_t)h * S_LEN + q0 + 2 * tr) * S_LEN;
    const float* row1 = row0 + S_LEN;

    for (int jc = 0; jc <= q0 + 31; jc += 32) {
#pragma unroll
        for (int p = 0; p < 4; p++) {
            int f4 = tid + p * 256;
            int vr = f4 >> 5;
            int vc = (f4 & 31) << 2;
            *(float4*)(&Vs[vr][vc]) =
                *(const float4*)(Vb + (size_t)(jc + vr) * NKD + kvh * HD + vc);
        }
        __syncthreads();

#pragma unroll 8
        for (int jj = 0; jj < 32; jj++) {
            float p0 = row0[jc + jj];
            float p1 = row1[jc + jj];
            float4 va = *(const float4*)(&Vs[jj][c0]);
            float4 vb = *(const float4*)(&Vs[jj][c0 + 4]);
            acc0[0] += p0 * va.x; acc0[1] += p0 * va.y;
            acc0[2] += p0 * va.z; acc0[3] += p0 * va.w;
            acc0[4] += p0 * vb.x; acc0[5] += p0 * vb.y;
            acc0[6] += p0 * vb.z; acc0[7] += p0 * vb.w;
            acc1[0] += p1 * va.x; acc1[1] += p1 * va.y;
            acc1[2] += p1 * va.z; acc1[3] += p1 * va.w;
            acc1[4] += p1 * vb.x; acc1[5] += p1 * vb.y;
            acc1[6] += p1 * vb.z; acc1[7] += p1 * vb.w;
        }
        __syncthreads();
    }

    float inv0 = 1.f / rsum[2 * tr];
    float inv1 = 1.f / rsum[2 * tr + 1];
    float* o0 = O + (size_t)(q0 + 2 * tr) * NQD + h * HD + c0;
    float* o1 = o0 + NQD;
    *(float4*)(o0)     = make_float4(acc0[0] * inv0, acc0[1] * inv0, acc0[2] * inv0, acc0[3] * inv0);
    *(float4*)(o0 + 4) = make_float4(acc0[4] * inv0, acc0[5] * inv0, acc0[6] * inv0, acc0[7] * inv0);
    *(float4*)(o1)     = make_float4(acc1[0] * inv1, acc1[1] * inv1, acc1[2] * inv1, acc1[3] * inv1);
    *(float4*)(o1 + 4) = make_float4(acc1[4] * inv1, acc1[5] * inv1, acc1[6] * inv1, acc1[7] * inv1);
}

// ---------------- launch ----------------
extern "C" void kernel_launch(void* const* d_in, const int* in_sizes, int n_in,
                              void* d_out, int out_size)
{
    (void)in_sizes; (void)n_in; (void)out_size;

    const float* H  = (const float*)d_in[0];
    const float* wq = (const float*)d_in[1];
    const float* wk = (const float*)d_in[2];
    const float* wv = (const float*)d_in[3];
    const float* wo = (const float*)d_in[4];
    float* out = (float*)d_out;

    float *Q, *K, *V, *O, *Sc;
    unsigned* Thr;
    cudaGetSymbolAddress((void**)&Q,   g_q);
    cudaGetSymbolAddress((void**)&K,   g_k);
    cudaGetSymbolAddress((void**)&V,   g_v);
    cudaGetSymbolAddress((void**)&O,   g_o);
    cudaGetSymbolAddress((void**)&Sc,  g_sc);
    cudaGetSymbolAddress((void**)&Thr, g_thr);

    // QKV projections
    sgemm_kernel<<<dim3(NQD / GBN, S_LEN / GBM), 256>>>(H, wq, Q, S_LEN, NQD, HID);
    sgemm_kernel<<<dim3(NKD / GBN, S_LEN / GBM), 256>>>(H, wk, K, S_LEN, NKD, HID);
    sgemm_kernel<<<dim3(NKD / GBN, S_LEN / GBM), 256>>>(H, wv, V, S_LEN, NKD, HID);

    // RoPE on Q and K
    rope_kernel<<<dim3(S_LEN, NH + NKV), 64>>>(Q, K);

    // raw attention scores (causal tiles only)
    scores_kernel<<<dim3(S_LEN / 64, S_LEN / 64, NH), 256>>>(Q, K, Sc);

    // heavy-hitter thresholds (rows 1152..2047)
    topk_kernel<<<dim3(NH, (S_LEN - 1152) / 8), 256>>>(Sc, Thr);

    // masked softmax + P@V
    attn_kernel<<<dim3(NH, S_LEN / 32), 256>>>(Sc, Thr, V, O);

    // output projection
    sgemm_kernel<<<dim3(HID / GBN, S_LEN / GBM), 256>>>(O, wo, out, S_LEN, HID, NQD);
}